// round 9
// baseline (speedup 1.0000x reference)
#include <cuda_runtime.h>
#include <cuda_bf16.h>
#include <cstdint>

// TSAdaptivePatcher: PATCH_SIZE == STRIDE == 16 -> non-overlapping windows.
//   x:    [B=64, C=64, S=8192] f32   (128 MiB vs 126 MB L2)
//   mask: [B=64, S=8192] i32 (0/1)   (2 MiB)
// Outputs (concatenated in d_out, f32):
//   patches      [B, 512, 1024] : patches[b,p,c*16+j] = x[b,c,p*16+j]
//   padding_mask [B, 512]       : (sum_{j<16} mask[b,p*16+j] >= 8) ? 1 : 0
//
// R8: partial L2 pinning. R7 showed pinning ALL of x (128MiB > 126MB L2)
// makes the pinned lines thrash each other. Instead pin only the first
// 96 MiB of x (fits, leaves headroom for the transiting write stream +
// mask); stream the remaining 32 MiB evict-first. Across graph replays the
// pinned set stays L2-resident -> per-replay DRAM traffic ~215MB -> ~162MB.
// Copy structure identical to the 43.8us R5 kernel (ILP=8, 512B/thread
// contiguous reads, linear writes, fused mask blocks, __stcs stores).

static constexpr int B = 64;
static constexpr int C = 64;
static constexpr int S = 8192;
static constexpr int NPATCH = 512;
static constexpr long PATCH_ELEMS = (long)B * NPATCH * C * 16;   // 33,554,432
static constexpr int N_COPY_V4 = (int)(PATCH_ELEMS / 4);         // 8,388,608 = 2^23
static constexpr int N_MASK = B * NPATCH;                        // 32,768

static constexpr int TPB = 256;
static constexpr int ILP = 8;
static constexpr int COPY_BLOCKS = N_COPY_V4 / (TPB * ILP);      // 4096
static constexpr int MASK_BLOCKS = N_MASK / TPB;                 // 128

// Pin the first 96 MiB of x: threshold in float4 units.
static constexpr int PIN_V4 = (96 << 20) / 16;                   // 6,291,456

__device__ __forceinline__ uint64_t policy_evict_last() {
    uint64_t pol;
    asm("createpolicy.fractional.L2::evict_last.b64 %0, 1.0;" : "=l"(pol));
    return pol;
}
__device__ __forceinline__ uint64_t policy_evict_first() {
    uint64_t pol;
    asm("createpolicy.fractional.L2::evict_first.b64 %0, 1.0;" : "=l"(pol));
    return pol;
}

__device__ __forceinline__ float4 ldg_hint_v4(const float4* p, uint64_t pol) {
    float4 v;
    asm volatile("ld.global.nc.L2::cache_hint.v4.f32 {%0,%1,%2,%3}, [%4], %5;"
                 : "=f"(v.x), "=f"(v.y), "=f"(v.z), "=f"(v.w)
                 : "l"(p), "l"(pol));
    return v;
}

__device__ __forceinline__ int4 ldg_hint_i4(const int4* p, uint64_t pol) {
    int4 v;
    asm volatile("ld.global.nc.L2::cache_hint.v4.s32 {%0,%1,%2,%3}, [%4], %5;"
                 : "=r"(v.x), "=r"(v.y), "=r"(v.z), "=r"(v.w)
                 : "l"(p), "l"(pol));
    return v;
}

__global__ void __launch_bounds__(TPB) fused_patcher_kernel(
    const float4* __restrict__ x,
    const int4*   __restrict__ mask,
    float4* __restrict__ out_patches,
    float*  __restrict__ out_mask)
{
    int bid = blockIdx.x;

    if (bid < MASK_BLOCKS) {
        // ---- mask reduction: i = b*512 + p ----
        uint64_t pol = policy_evict_last();      // 2MB, reused every replay
        int i = bid * TPB + threadIdx.x;
        const int4* mp = mask + (i << 2);        // 16 contiguous ints per patch
        int s = 0;
#pragma unroll
        for (int k = 0; k < 4; k++) {
            int4 v = ldg_hint_i4(mp + k, pol);
            s += v.x + v.y + v.z + v.w;
        }
        // valid_ratio >= 0.5  <=>  integer sum >= 8 (exact)
        out_mask[i] = (s >= 8) ? 1.0f : 0.0f;
        return;
    }

    // ---- streaming permutation, output-linear, ILP=8 ----
    int cb = bid - MASK_BLOCKS;
    int base = cb * (TPB * ILP) + threadIdx.x;

    // Decode source once; i += TPB(=256) increments the p field (bit 8),
    // so src advances by 4 float4s (64B) per k: contiguous per-thread reads.
    int i0 = base;
    int jv = i0 & 3;
    int c  = (i0 >> 2) & 63;
    int p  = (i0 >> 8) & 511;
    int b  = i0 >> 17;
    int src0 = (((b << 6) + c) << 11) + (p << 2) + jv;

    // First 96MiB of x: evict_last (stays resident across graph replays).
    // Last 32MiB: evict_first (pure stream). The whole 8-load run of one
    // thread sits inside one c-row, so one test covers all 8 loads.
    uint64_t pol = (src0 < PIN_V4) ? policy_evict_last() : policy_evict_first();

    float4 v[ILP];
#pragma unroll
    for (int k = 0; k < ILP; k++)
        v[k] = ldg_hint_v4(x + src0 + k * 4, pol);
#pragma unroll
    for (int k = 0; k < ILP; k++)
        __stcs(out_patches + base + k * TPB, v[k]);  // writes pass through
}

extern "C" void kernel_launch(void* const* d_in, const int* in_sizes, int n_in,
                              void* d_out, int out_size)
{
    (void)in_sizes; (void)n_in; (void)out_size;
    const float4* x    = (const float4*)d_in[0];
    const int4*   mask = (const int4*)d_in[1];
    float* out = (float*)d_out;

    fused_patcher_kernel<<<MASK_BLOCKS + COPY_BLOCKS, TPB>>>(
        x, mask, (float4*)out, out + PATCH_ELEMS);
}

// round 11
// speedup vs baseline: 1.0286x; 1.0286x over previous
#include <cuda_runtime.h>
#include <cuda_bf16.h>
#include <cstdint>

// TSAdaptivePatcher: PATCH_SIZE == STRIDE == 16 -> non-overlapping windows.
//   x:    [B=64, C=64, S=8192] f32
//   mask: [B=64, S=8192] i32 (0/1)
// Outputs (concatenated in d_out, f32):
//   patches      [B, 512, 1024] : patches[b,p,c*16+j] = x[b,c,p*16+j]
//   padding_mask [B, 512]       : (sum_{j<16} mask[b,p*16+j] >= 8) ? 1 : 0
//
// R9: cache-policy experiments (R7/R8) regressed -> reverted. This round:
// 256-bit global accesses (LDG.256/STG.256, sm_103a supports .v8.b32).
// Copy works in float8 (32B) units: ILP=4 x 32B per thread, warp-level
// transactions are 1KB contiguous on BOTH sides, half the instructions and
// L1tex wavefronts per byte vs the 43.8us float4 kernel. Mask blocks fused
// at low blockIdx as before.

static constexpr int B = 64;
static constexpr int C = 64;
static constexpr int S = 8192;
static constexpr int NPATCH = 512;
static constexpr long PATCH_ELEMS = (long)B * NPATCH * C * 16;   // 33,554,432
static constexpr int N_COPY_V8 = (int)(PATCH_ELEMS / 8);         // 4,194,304 = 2^22
static constexpr int N_MASK = B * NPATCH;                        // 32,768

static constexpr int TPB = 256;
static constexpr int ILP = 4;
static constexpr int COPY_BLOCKS = N_COPY_V8 / (TPB * ILP);      // 4096
static constexpr int MASK_BLOCKS = N_MASK / TPB;                 // 128

struct f8 { uint32_t r[8]; };

__device__ __forceinline__ void ldg256(f8& v, const void* p) {
    asm volatile("ld.global.nc.v8.b32 {%0,%1,%2,%3,%4,%5,%6,%7}, [%8];"
                 : "=r"(v.r[0]), "=r"(v.r[1]), "=r"(v.r[2]), "=r"(v.r[3]),
                   "=r"(v.r[4]), "=r"(v.r[5]), "=r"(v.r[6]), "=r"(v.r[7])
                 : "l"(p));
}

__device__ __forceinline__ void stg256_cs(void* p, const f8& v) {
    asm volatile("st.global.cs.v8.b32 [%0], {%1,%2,%3,%4,%5,%6,%7,%8};"
                 :: "l"(p),
                    "r"(v.r[0]), "r"(v.r[1]), "r"(v.r[2]), "r"(v.r[3]),
                    "r"(v.r[4]), "r"(v.r[5]), "r"(v.r[6]), "r"(v.r[7])
                 : "memory");
}

__global__ void __launch_bounds__(TPB) fused_patcher_kernel(
    const float* __restrict__ x,
    const int4*  __restrict__ mask,
    float* __restrict__ out_patches,
    float* __restrict__ out_mask)
{
    int bid = blockIdx.x;

    if (bid < MASK_BLOCKS) {
        // ---- mask reduction: i = b*512 + p ----
        int i = bid * TPB + threadIdx.x;
        const int4* mp = mask + (i << 2);        // 16 contiguous ints per patch
        int s = 0;
#pragma unroll
        for (int k = 0; k < 4; k++) {
            int4 v = __ldcs(mp + k);
            s += v.x + v.y + v.z + v.w;
        }
        // valid_ratio >= 0.5  <=>  integer sum >= 8 (exact)
        out_mask[i] = (s >= 8) ? 1.0f : 0.0f;
        return;
    }

    // ---- streaming permutation in float8 (32B) units, ILP=4 ----
    int cb = bid - MASK_BLOCKS;
    int base = cb * (TPB * ILP) + threadIdx.x;   // output-linear float8 index

    // float8-index bit layout: [b:6][p:9][c:6][jv8:1]
    // src (float8 units): (b*64 + c)*1024 + p*2 + jv8
    // k*TPB(=256) steps j8 bit 8 -> p += 2 -> src += 4 per k (same b,c:
    // block range (4096 j8) stays inside one 2^16 b-window; no field carry).
    int i0  = base;
    int jv8 = i0 & 1;
    int c   = (i0 >> 1) & 63;
    int p   = (i0 >> 7) & 511;
    int b   = i0 >> 16;
    long src0 = ((long)((b << 6) + c) << 10) + (p << 1) + jv8;   // float8 units

    f8 v[ILP];
#pragma unroll
    for (int k = 0; k < ILP; k++)
        ldg256(v[k], x + ((src0 + 4L * k) << 3));
#pragma unroll
    for (int k = 0; k < ILP; k++)
        stg256_cs(out_patches + ((long)(base + k * TPB) << 3), v[k]);
}

extern "C" void kernel_launch(void* const* d_in, const int* in_sizes, int n_in,
                              void* d_out, int out_size)
{
    (void)in_sizes; (void)n_in; (void)out_size;
    const float* x    = (const float*)d_in[0];
    const int4*  mask = (const int4*)d_in[1];
    float* out = (float*)d_out;

    fused_patcher_kernel<<<MASK_BLOCKS + COPY_BLOCKS, TPB>>>(
        x, mask, out, out + PATCH_ELEMS);
}